// round 7
// baseline (speedup 1.0000x reference)
#include <cuda_runtime.h>
#include <cstdint>

#define VN 128
#define NTHREADS 256
#define NBUF 4
#define CHUNK_BYTES 10240            // 10KB = 4 edge rows (4*128*5*4)
#define CHUNK_FLOATS 2560
#define NCHUNK 32

// collapsed constants: [0:5]gn1 [5:10]gn2 [10:18]d1 [18:26]d2 [26:36]ac
//                      [36]k1 [37]k2 [38]K
__device__ float g_cst[43];
__device__ float g_sums[512 * 28];
__device__ int   g_count = 0;

// ---------------- mbarrier + TMA bulk helpers ----------------
__device__ __forceinline__ void mbar_init(uint32_t mbar, uint32_t count) {
    asm volatile("mbarrier.init.shared.b64 [%0], %1;" :: "r"(mbar), "r"(count)
                 : "memory");
}
__device__ __forceinline__ void mbar_expect_tx(uint32_t mbar, uint32_t bytes) {
    asm volatile("mbarrier.arrive.expect_tx.shared.b64 _, [%0], %1;"
                 :: "r"(mbar), "r"(bytes) : "memory");
}
__device__ __forceinline__ void mbar_arrive(uint32_t mbar) {
    asm volatile("mbarrier.arrive.shared.b64 _, [%0];" :: "r"(mbar) : "memory");
}
__device__ __forceinline__ void tma_bulk_g2s(uint32_t dst, const void* src,
                                             uint32_t bytes, uint32_t mbar) {
    asm volatile(
        "cp.async.bulk.shared::cta.global.mbarrier::complete_tx::bytes "
        "[%0], [%1], %2, [%3];"
        :: "r"(dst), "l"(src), "r"(bytes), "r"(mbar) : "memory");
}
// suspended (non-spinning) waits, per canonical pattern
__device__ __forceinline__ void mbar_wait_acq(uint32_t mbar, uint32_t parity) {
    asm volatile(
        "{\n\t.reg .pred P;\n\t"
        "WL_%=:\n\t"
        "mbarrier.try_wait.parity.acquire.cta.shared::cta.b64 P, [%0], %1, 0x989680;\n\t"
        "@!P bra WL_%=;\n\t"
        "}" :: "r"(mbar), "r"(parity) : "memory");
}
__device__ __forceinline__ void mbar_wait_rlx(uint32_t mbar, uint32_t parity) {
    asm volatile(
        "{\n\t.reg .pred P;\n\t"
        "WL_%=:\n\t"
        "mbarrier.try_wait.parity.relaxed.cta.shared::cta.b64 P, [%0], %1, 0x989680;\n\t"
        "@!P bra WL_%=;\n\t"
        "}" :: "r"(mbar), "r"(parity) : "memory");
}

// ---------------------------------------------------------------------------
// Task-parallel matvec (low-latency): out[k] = sum_m W[k*M+m] v[m].
// ---------------------------------------------------------------------------
__device__ __forceinline__ void mvp(const float* __restrict__ W, const float* v,
                                    float* out, int K, int M, float* psum) {
    const int tid   = threadIdx.x;
    const int chunk = (M < 32) ? M : 32;
    const int nch   = M / chunk;
    const int tasks = K * nch;
    for (int t = tid; t < tasks; t += NTHREADS) {
        int k = t / nch, c = t - k * nch;
        const float* wr = W + k * M + c * chunk;
        const float* vv = v + c * chunk;
        float acc = 0.f;
        #pragma unroll
        for (int m = 0; m < 32; m++) {
            if (m < chunk) acc += wr[m] * vv[m];
        }
        psum[t] = acc;
    }
    __syncthreads();
    for (int k = tid; k < K; k += NTHREADS) {
        float acc = 0.f;
        for (int c = 0; c < nch; c++) acc += psum[k * nch + c];
        out[k] = acc;
    }
    __syncthreads();
}

__device__ __forceinline__ float warp_dot(const float* __restrict__ a,
                                          const float* b, int n, int lane) {
    float acc = 0.f;
    for (int i = lane; i < n; i += 32) acc += a[i] * b[i];
    #pragma unroll
    for (int o = 16; o; o >>= 1) acc += __shfl_xor_sync(0xffffffffu, acc, o);
    return acc;
}

// ---------------------------------------------------------------------------
// Weight collapse (block 0 only). Writes 43 floats to g_cst.
// ---------------------------------------------------------------------------
__device__ void collapse_weights(
    float* sm,
    const float* __restrict__ w_ne0, const float* __restrict__ b_ne0,
    const float* __restrict__ w_ne1, const float* __restrict__ b_ne1,
    const float* __restrict__ w_g1,  const float* __restrict__ b_g1,
    const float* __restrict__ w_g2,  const float* __restrict__ b_g2,
    const float* __restrict__ w_g3a, const float* __restrict__ b_g3a,
    const float* __restrict__ w_g3b, const float* __restrict__ b_g3b,
    const float* __restrict__ w_ce0, const float* __restrict__ b_ce0,
    const float* __restrict__ w_ce1, const float* __restrict__ b_ce1,
    const float* __restrict__ w_f0,  const float* __restrict__ b_f0,
    const float* __restrict__ w_f1,  const float* __restrict__ b_f1,
    const float* __restrict__ w_f2,  const float* __restrict__ b_f2,
    const float* __restrict__ w_f3,  const float* __restrict__ b_f3)
{
    float* v3   = sm;          // 32
    float* v2   = v3 + 32;     // 64
    float* v1   = v2 + 64;     // 128
    float* wfv  = v1 + 128;    // 160 (144 used)
    float* t16  = wfv + 160;   // 32
    float* evec = t16 + 32;    // 256
    float* fvec = evec + 256;  // 128
    float* tmp64= fvec + 128;  // 64
    float* a1   = tmp64 + 64;  // 32
    float* a2   = a1 + 32;     // 32
    float* g1a  = a2 + 32;     // 40
    float* g1b  = g1a + 40;    // 40
    float* ng1  = g1b + 40;    // 64
    float* ng2  = ng1 + 64;    // 64
    float* d1v  = ng2 + 64;    // 8
    float* d2v  = d1v + 8;     // 8
    float* acv  = d2v + 8;     // 12
    float* kres = acv + 12;    // 16
    float* psum = kres + 16;   // 1024

    const int tid = threadIdx.x, wid = tid >> 5, lane = tid & 31;

    if (tid < 32) v3[tid] = w_f3[tid];
    __syncthreads();
    mvp(w_f2, v3, v2, 64, 32, psum);
    mvp(w_f1, v2, v1, 128, 64, psum);
    mvp(w_f0, v1, wfv, 144, 128, psum);       // [0:128]=Wfg, [128:144]=Wfc
    mvp(w_g3b, wfv, evec, 256, 128, psum);
    mvp(w_ce1, wfv + 128, t16, 32, 16, psum);
    mvp(w_g3a, evec, fvec, 128, 256, psum);
    mvp(w_ce0, t16, acv, 10, 32, psum);
    if (tid < 64) tmp64[tid] = fvec[tid] + fvec[64 + tid];
    __syncthreads();
    mvp(w_g2, tmp64, a1, 32, 64, psum);
    mvp(w_g2, fvec + 64, a2, 32, 64, psum);
    if (tid < 32) a2[tid] = -a2[tid];
    __syncthreads();
    mvp(w_g1, a1, g1a, 37, 32, psum);
    mvp(w_g1, a2, g1b, 37, 32, psum);
    mvp(w_ne1, g1a + 5, ng1, 64, 32, psum);
    mvp(w_ne1, g1b + 5, ng2, 64, 32, psum);
    mvp(w_ne0, ng1, d1v, 8, 64, psum);
    mvp(w_ne0, ng2, d2v, 8, 64, psum);

    for (int o = wid; o < 14; o += 8) {
        float r;
        switch (o) {
            case 0:  r = warp_dot(b_f2, v3, 32, lane); break;
            case 1:  r = warp_dot(b_f1, v2, 64, lane); break;
            case 2:  r = warp_dot(b_f0, v1, 128, lane); break;
            case 3:  r = warp_dot(b_ce0, t16, 32, lane); break;
            case 4:  r = warp_dot(b_ce1, wfv + 128, 16, lane); break;
            case 5:  r = warp_dot(b_g2, fvec, 64, lane); break;
            case 6:  r = warp_dot(b_g3a, evec, 256, lane); break;
            case 7:  r = warp_dot(b_g3b, wfv, 128, lane); break;
            case 8:  r = warp_dot(b_g1, a1, 32, lane); break;
            case 9:  r = warp_dot(b_ne0, ng1, 64, lane); break;
            case 10: r = warp_dot(b_ne1, g1a + 5, 32, lane); break;
            case 11: r = warp_dot(b_g1, a2, 32, lane); break;
            case 12: r = warp_dot(b_ne0, ng2, 64, lane); break;
            default: r = warp_dot(b_ne1, g1b + 5, 32, lane); break;
        }
        if (lane == 0) kres[o] = r;
    }
    __syncthreads();

    if (tid < 5)  { g_cst[tid] = g1a[tid]; g_cst[5 + tid] = g1b[tid]; }
    if (tid < 8)  { g_cst[10 + tid] = d1v[tid]; g_cst[18 + tid] = d2v[tid]; }
    if (tid < 10) g_cst[26 + tid] = acv[tid];
    if (tid == 0) {
        g_cst[36] = kres[8] + kres[9] + kres[10];
        g_cst[37] = kres[11] + kres[12] + kres[13];
        g_cst[38] = kres[0] + kres[1] + kres[2] + kres[3] + kres[4]
                  + kres[5] + kres[6] + kres[7] + b_f3[0];
    }
}

// ---------------------------------------------------------------------------
// grid 513. Block 0: weight collapse. Blocks 1..512: batch b-1.
// Streaming: 32 x 10KB chunks, 4-deep TMA bulk pipeline with full/empty
// mbarrier pairs, suspended waits, NO __syncthreads in the loop.
// Consume: 2 outputs/thread, scalar LDS (stride-5, conflict-free).
// smem floats: Asum 16384 | stage 4x2560 | deg/w0/rA/rB 512 | mbars 16
// = 27152 floats = 108608 B  (2 blocks/SM)
// ---------------------------------------------------------------------------
#define SMEM_FLOATS (16384 + NBUF * CHUNK_FLOATS + 512 + 16)
#define SMEM_BYTES  (SMEM_FLOATS * 4)

__global__ __launch_bounds__(NTHREADS, 2) void gnn_fused(
    const float* __restrict__ edges,
    const float* __restrict__ nodes,
    const float* __restrict__ nparams,
    const float* __restrict__ cond,
    float* __restrict__ out,
    const float* w_ne0, const float* b_ne0, const float* w_ne1, const float* b_ne1,
    const float* w_g1,  const float* b_g1,  const float* w_g2,  const float* b_g2,
    const float* w_g3a, const float* b_g3a, const float* w_g3b, const float* b_g3b,
    const float* w_ce0, const float* b_ce0, const float* w_ce1, const float* b_ce1,
    const float* w_f0,  const float* b_f0,  const float* w_f1,  const float* b_f1,
    const float* w_f2,  const float* b_f2,  const float* w_f3,  const float* b_f3)
{
    extern __shared__ float sm[];
    const int tid = threadIdx.x;
    const int wid = tid >> 5, lane = tid & 31;

    if (blockIdx.x == 0) {
        collapse_weights(sm,
                         w_ne0, b_ne0, w_ne1, b_ne1, w_g1, b_g1, w_g2, b_g2,
                         w_g3a, b_g3a, w_g3b, b_g3b, w_ce0, b_ce0, w_ce1, b_ce1,
                         w_f0, b_f0, w_f1, b_f1, w_f2, b_f2, w_f3, b_f3);
    } else {
        const int b = blockIdx.x - 1;
        float* Asum  = sm;                         // 16384
        float* stage = Asum + 16384;               // 4 x 2560
        float* deg   = stage + NBUF * CHUNK_FLOATS;// 128
        float* w0    = deg + 128;                  // 128
        float* rA    = w0 + 128;                   // 128
        float* rB    = rA + 128;                   // 128
        float* mbarf = rB + 128;                   // 16 floats = 8 mbarriers

        const char* src = (const char*)(edges + (size_t)b * VN * VN * 5);
        const uint32_t stage_s = (uint32_t)__cvta_generic_to_shared(stage);
        const uint32_t mb_base = (uint32_t)__cvta_generic_to_shared(mbarf);
        // full[i] = mb_base + i*8 ; empty[i] = mb_base + 32 + i*8

        if (tid == 0) {
            #pragma unroll
            for (int i = 0; i < NBUF; i++) {
                mbar_init(mb_base + i * 8, 1);            // full: 1 producer
                mbar_init(mb_base + 32 + i * 8, NTHREADS);// empty: all consumers
            }
        }
        __syncthreads();

        // prologue: fill all 4 buffers
        if (tid == 0) {
            #pragma unroll
            for (int i = 0; i < NBUF; i++) {
                mbar_expect_tx(mb_base + i * 8, CHUNK_BYTES);
                tma_bulk_g2s(stage_s + i * CHUNK_BYTES,
                             src + (size_t)i * CHUNK_BYTES,
                             CHUNK_BYTES, mb_base + i * 8);
            }
        }

        for (int ch = 0; ch < NCHUNK; ch++) {
            const int buf = ch & (NBUF - 1);
            const int k   = ch >> 2;              // round index
            const uint32_t mb_full  = mb_base + buf * 8;
            const uint32_t mb_empty = mb_base + 32 + buf * 8;

            mbar_wait_acq(mb_full, k & 1);

            // consume: chunk = 4 rows x 128 cols; 2 outputs per thread
            const float* sb = stage + buf * CHUNK_FLOATS;
            #pragma unroll
            for (int h = 0; h < 2; h++) {
                int o  = tid + h * NTHREADS;      // 0..511
                int ri = o >> 7;
                int j  = o & 127;
                const float* s = sb + ri * 640 + 5 * j;
                Asum[(ch * 4 + ri) * VN + j] = s[1] + s[2] + s[3] + s[4];
            }
            mbar_arrive(mb_empty);

            // producer: refill this buffer with chunk ch+4
            if (tid == 0 && ch + NBUF < NCHUNK) {
                mbar_wait_rlx(mb_empty, k & 1);   // all 256 arrivals this round
                mbar_expect_tx(mb_full, CHUNK_BYTES);
                tma_bulk_g2s(stage_s + buf * CHUNK_BYTES,
                             src + (size_t)(ch + NBUF) * CHUNK_BYTES,
                             CHUNK_BYTES, mb_full);
            }
        }
        __syncthreads();

        // ---- deg[i] = row sum; w0 = 1/(V*deg) ----
        for (int i = wid; i < VN; i += 8) {
            float acc = 0.f;
            #pragma unroll
            for (int u = 0; u < 4; u++) acc += Asum[i * VN + lane + 32 * u];
            #pragma unroll
            for (int o = 16; o; o >>= 1)
                acc += __shfl_xor_sync(0xffffffffu, acc, o);
            if (lane == 0) {
                float d = fmaxf(acc, 1e-8f);
                deg[i] = d;
                w0[i]  = 1.f / (d * (float)VN);
            }
        }
        __syncthreads();

        // ---- r1 = Asum^T w0 ; r2 ; r3 ----
        if (tid < VN) {
            float acc = 0.f;
            #pragma unroll 8
            for (int i = 0; i < VN; i++) acc += Asum[i * VN + tid] * w0[i];
            rA[tid] = acc;                       // r1
        }
        __syncthreads();
        if (tid < VN) w0[tid] = rA[tid] / deg[tid];
        __syncthreads();
        if (tid < VN) {
            float acc = 0.f;
            #pragma unroll 8
            for (int i = 0; i < VN; i++) acc += Asum[i * VN + tid] * w0[i];
            rA[tid] = acc;                       // r2
        }
        __syncthreads();
        if (tid < VN) w0[tid] = rA[tid] / deg[tid];
        __syncthreads();
        if (tid < VN) {
            float acc = 0.f;
            #pragma unroll 8
            for (int i = 0; i < VN; i++) acc += Asum[i * VN + tid] * w0[i];
            rB[tid] = acc;                       // r3
        }
        __syncthreads();

        // ---- 28 weight-independent sums -> g_sums ----
        for (int o = wid; o < 28; o += 8) {
            const float* r = (o >= 14) ? rB : rA;
            int m = (o >= 14) ? o - 14 : o;
            float acc = 0.f;
            #pragma unroll 4
            for (int j = lane; j < VN; j += 32) {
                float x;
                if (m < 5)       x = nodes[((size_t)b * VN + j) * 5 + m];
                else if (m < 13) x = nparams[((size_t)b * VN + j) * 8 + (m - 5)];
                else             x = 1.f;
                acc += r[j] * x;
            }
            #pragma unroll
            for (int off = 16; off; off >>= 1)
                acc += __shfl_xor_sync(0xffffffffu, acc, off);
            if (lane == 0) g_sums[b * 28 + o] = acc;
        }
    }

    // ---- last-block combine ----
    __threadfence();
    __syncthreads();
    __shared__ int s_old;
    if (tid == 0) s_old = atomicAdd(&g_count, 1);
    __syncthreads();
    if (s_old == 512) {
        float c[43];
        #pragma unroll
        for (int i = 0; i < 43; i++) c[i] = __ldcg(&g_cst[i]);
        for (int b2 = tid; b2 < 512; b2 += NTHREADS) {
            const float* S = &g_sums[b2 * 28];
            float acc = c[38] + c[36] * __ldcg(&S[13]) + c[37] * __ldcg(&S[27]);
            #pragma unroll
            for (int m = 0; m < 5; m++)
                acc += c[m] * __ldcg(&S[m]) + c[5 + m] * __ldcg(&S[14 + m]);
            #pragma unroll
            for (int m = 0; m < 8; m++)
                acc += c[10 + m] * __ldcg(&S[5 + m]) + c[18 + m] * __ldcg(&S[19 + m]);
            const float* cd = cond + (size_t)b2 * 10;
            #pragma unroll
            for (int m = 0; m < 10; m++) acc += c[26 + m] * cd[m];
            out[b2] = acc;
        }
        if (tid == 0) g_count = 0;   // reset for next graph replay
    }
}

extern "C" void kernel_launch(void* const* d_in, const int* in_sizes, int n_in,
                              void* d_out, int out_size) {
    cudaFuncSetAttribute(gnn_fused, cudaFuncAttributeMaxDynamicSharedMemorySize,
                         SMEM_BYTES);

    gnn_fused<<<513, NTHREADS, SMEM_BYTES>>>(
        (const float*)d_in[0], (const float*)d_in[1],
        (const float*)d_in[2], (const float*)d_in[3],
        (float*)d_out,
        (const float*)d_in[4],  (const float*)d_in[5],
        (const float*)d_in[6],  (const float*)d_in[7],
        (const float*)d_in[8],  (const float*)d_in[9],
        (const float*)d_in[10], (const float*)d_in[11],
        (const float*)d_in[12], (const float*)d_in[13],
        (const float*)d_in[14], (const float*)d_in[15],
        (const float*)d_in[16], (const float*)d_in[17],
        (const float*)d_in[18], (const float*)d_in[19],
        (const float*)d_in[20], (const float*)d_in[21],
        (const float*)d_in[22], (const float*)d_in[23],
        (const float*)d_in[24], (const float*)d_in[25],
        (const float*)d_in[26], (const float*)d_in[27]);
}

// round 8
// speedup vs baseline: 1.0481x; 1.0481x over previous
#include <cuda_runtime.h>
#include <cstdint>

#define VN 128
#define NTHREADS 256

// collapsed constants: [0:5]gn1 [5:10]gn2 [10:18]d1 [18:26]d2 [26:36]ac
//                      [36]k1 [37]k2 [38]K
__device__ float g_cst[43];
__device__ float g_sums[512 * 28];
__device__ int   g_count = 0;

// ---------------------------------------------------------------------------
// Task-parallel matvec (low-latency): out[k] = sum_m W[k*M+m] v[m].
// ---------------------------------------------------------------------------
__device__ __forceinline__ void mvp(const float* __restrict__ W, const float* v,
                                    float* out, int K, int M, float* psum) {
    const int tid   = threadIdx.x;
    const int chunk = (M < 32) ? M : 32;
    const int nch   = M / chunk;
    const int tasks = K * nch;
    for (int t = tid; t < tasks; t += NTHREADS) {
        int k = t / nch, c = t - k * nch;
        const float* wr = W + k * M + c * chunk;
        const float* vv = v + c * chunk;
        float acc = 0.f;
        #pragma unroll
        for (int m = 0; m < 32; m++) {
            if (m < chunk) acc += wr[m] * vv[m];
        }
        psum[t] = acc;
    }
    __syncthreads();
    for (int k = tid; k < K; k += NTHREADS) {
        float acc = 0.f;
        for (int c = 0; c < nch; c++) acc += psum[k * nch + c];
        out[k] = acc;
    }
    __syncthreads();
}

__device__ __forceinline__ float warp_dot(const float* __restrict__ a,
                                          const float* b, int n, int lane) {
    float acc = 0.f;
    for (int i = lane; i < n; i += 32) acc += a[i] * b[i];
    #pragma unroll
    for (int o = 16; o; o >>= 1) acc += __shfl_xor_sync(0xffffffffu, acc, o);
    return acc;
}

// ---------------------------------------------------------------------------
// Weight collapse (block 0 only). Writes 43 floats to g_cst.
// ---------------------------------------------------------------------------
__device__ void collapse_weights(
    float* sm,
    const float* __restrict__ w_ne0, const float* __restrict__ b_ne0,
    const float* __restrict__ w_ne1, const float* __restrict__ b_ne1,
    const float* __restrict__ w_g1,  const float* __restrict__ b_g1,
    const float* __restrict__ w_g2,  const float* __restrict__ b_g2,
    const float* __restrict__ w_g3a, const float* __restrict__ b_g3a,
    const float* __restrict__ w_g3b, const float* __restrict__ b_g3b,
    const float* __restrict__ w_ce0, const float* __restrict__ b_ce0,
    const float* __restrict__ w_ce1, const float* __restrict__ b_ce1,
    const float* __restrict__ w_f0,  const float* __restrict__ b_f0,
    const float* __restrict__ w_f1,  const float* __restrict__ b_f1,
    const float* __restrict__ w_f2,  const float* __restrict__ b_f2,
    const float* __restrict__ w_f3,  const float* __restrict__ b_f3)
{
    float* v3   = sm;          // 32
    float* v2   = v3 + 32;     // 64
    float* v1   = v2 + 64;     // 128
    float* wfv  = v1 + 128;    // 160 (144 used)
    float* t16  = wfv + 160;   // 32
    float* evec = t16 + 32;    // 256
    float* fvec = evec + 256;  // 128
    float* tmp64= fvec + 128;  // 64
    float* a1   = tmp64 + 64;  // 32
    float* a2   = a1 + 32;     // 32
    float* g1a  = a2 + 32;     // 40
    float* g1b  = g1a + 40;    // 40
    float* ng1  = g1b + 40;    // 64
    float* ng2  = ng1 + 64;    // 64
    float* d1v  = ng2 + 64;    // 8
    float* d2v  = d1v + 8;     // 8
    float* acv  = d2v + 8;     // 12
    float* kres = acv + 12;    // 16
    float* psum = kres + 16;   // 1024

    const int tid = threadIdx.x, wid = tid >> 5, lane = tid & 31;

    if (tid < 32) v3[tid] = w_f3[tid];
    __syncthreads();
    mvp(w_f2, v3, v2, 64, 32, psum);
    mvp(w_f1, v2, v1, 128, 64, psum);
    mvp(w_f0, v1, wfv, 144, 128, psum);       // [0:128]=Wfg, [128:144]=Wfc
    mvp(w_g3b, wfv, evec, 256, 128, psum);
    mvp(w_ce1, wfv + 128, t16, 32, 16, psum);
    mvp(w_g3a, evec, fvec, 128, 256, psum);
    mvp(w_ce0, t16, acv, 10, 32, psum);
    if (tid < 64) tmp64[tid] = fvec[tid] + fvec[64 + tid];
    __syncthreads();
    mvp(w_g2, tmp64, a1, 32, 64, psum);
    mvp(w_g2, fvec + 64, a2, 32, 64, psum);
    if (tid < 32) a2[tid] = -a2[tid];
    __syncthreads();
    mvp(w_g1, a1, g1a, 37, 32, psum);
    mvp(w_g1, a2, g1b, 37, 32, psum);
    mvp(w_ne1, g1a + 5, ng1, 64, 32, psum);
    mvp(w_ne1, g1b + 5, ng2, 64, 32, psum);
    mvp(w_ne0, ng1, d1v, 8, 64, psum);
    mvp(w_ne0, ng2, d2v, 8, 64, psum);

    for (int o = wid; o < 14; o += 8) {
        float r;
        switch (o) {
            case 0:  r = warp_dot(b_f2, v3, 32, lane); break;
            case 1:  r = warp_dot(b_f1, v2, 64, lane); break;
            case 2:  r = warp_dot(b_f0, v1, 128, lane); break;
            case 3:  r = warp_dot(b_ce0, t16, 32, lane); break;
            case 4:  r = warp_dot(b_ce1, wfv + 128, 16, lane); break;
            case 5:  r = warp_dot(b_g2, fvec, 64, lane); break;
            case 6:  r = warp_dot(b_g3a, evec, 256, lane); break;
            case 7:  r = warp_dot(b_g3b, wfv, 128, lane); break;
            case 8:  r = warp_dot(b_g1, a1, 32, lane); break;
            case 9:  r = warp_dot(b_ne0, ng1, 64, lane); break;
            case 10: r = warp_dot(b_ne1, g1a + 5, 32, lane); break;
            case 11: r = warp_dot(b_g1, a2, 32, lane); break;
            case 12: r = warp_dot(b_ne0, ng2, 64, lane); break;
            default: r = warp_dot(b_ne1, g1b + 5, 32, lane); break;
        }
        if (lane == 0) kres[o] = r;
    }
    __syncthreads();

    if (tid < 5)  { g_cst[tid] = g1a[tid]; g_cst[5 + tid] = g1b[tid]; }
    if (tid < 8)  { g_cst[10 + tid] = d1v[tid]; g_cst[18 + tid] = d2v[tid]; }
    if (tid < 10) g_cst[26 + tid] = acv[tid];
    if (tid == 0) {
        g_cst[36] = kres[8] + kres[9] + kres[10];
        g_cst[37] = kres[11] + kres[12] + kres[13];
        g_cst[38] = kres[0] + kres[1] + kres[2] + kres[3] + kres[4]
                  + kres[5] + kres[6] + kres[7] + b_f3[0];
    }
}

// ---------------------------------------------------------------------------
// grid 513. Block 0: weight collapse. Blocks 1..512: batch b-1.
// Streaming: 16 x 20KB chunks. Coalesced plain LDG.128 into registers
// (double-buffered), regs -> smem stage (alternating buffers), consume via
// 5x LDS.128 -> 4 sums -> 1x STS.128 into Asum. ONE __syncthreads per chunk;
// LDG latency of chunk k+1 hides under consume+store of chunk k.
// smem floats: Asum 16384 | stage 2x5120 | deg/w0/rA/rB 512 = 108544 B
// ---------------------------------------------------------------------------
#define SMEM_FLOATS (16384 + 10240 + 512)
#define SMEM_BYTES  (SMEM_FLOATS * 4)

__global__ __launch_bounds__(NTHREADS, 2) void gnn_fused(
    const float* __restrict__ edges,
    const float* __restrict__ nodes,
    const float* __restrict__ nparams,
    const float* __restrict__ cond,
    float* __restrict__ out,
    const float* w_ne0, const float* b_ne0, const float* w_ne1, const float* b_ne1,
    const float* w_g1,  const float* b_g1,  const float* w_g2,  const float* b_g2,
    const float* w_g3a, const float* b_g3a, const float* w_g3b, const float* b_g3b,
    const float* w_ce0, const float* b_ce0, const float* w_ce1, const float* b_ce1,
    const float* w_f0,  const float* b_f0,  const float* w_f1,  const float* b_f1,
    const float* w_f2,  const float* b_f2,  const float* w_f3,  const float* b_f3)
{
    extern __shared__ float sm[];
    const int tid = threadIdx.x;
    const int wid = tid >> 5, lane = tid & 31;

    if (blockIdx.x == 0) {
        collapse_weights(sm,
                         w_ne0, b_ne0, w_ne1, b_ne1, w_g1, b_g1, w_g2, b_g2,
                         w_g3a, b_g3a, w_g3b, b_g3b, w_ce0, b_ce0, w_ce1, b_ce1,
                         w_f0, b_f0, w_f1, b_f1, w_f2, b_f2, w_f3, b_f3);
    } else {
        const int b = blockIdx.x - 1;
        float* Asum  = sm;               // 16384
        float* stage = Asum + 16384;     // 2 x 5120
        float* deg   = stage + 10240;    // 128
        float* w0    = deg + 128;        // 128
        float* rA    = w0 + 128;         // 128
        float* rB    = rA + 128;         // 128

        const float4* src = (const float4*)(edges + (size_t)b * VN * VN * 5);

        // prologue: chunk 0 -> regs -> stage buf 0
        float4 rr[5];
        #pragma unroll
        for (int k = 0; k < 5; k++) rr[k] = src[tid + NTHREADS * k];
        {
            float4* d4 = (float4*)stage;
            #pragma unroll
            for (int k = 0; k < 5; k++) d4[tid + NTHREADS * k] = rr[k];
        }
        __syncthreads();

        for (int ch = 0; ch < 16; ch++) {
            // issue loads for chunk ch+1 early (coalesced LDG.128)
            if (ch < 15) {
                const float4* s4 = src + (ch + 1) * 1280;
                #pragma unroll
                for (int k = 0; k < 5; k++) rr[k] = s4[tid + NTHREADS * k];
            }
            // consume stage[ch&1]: thread t -> floats [20t,20t+20) = 4 vectors
            const float4* sb4 = (const float4*)(stage + (ch & 1) * 5120) + tid * 5;
            float4 e0 = sb4[0], e1 = sb4[1], e2 = sb4[2], e3 = sb4[3], e4 = sb4[4];
            float4 o4;
            o4.x = e0.y + e0.z + e0.w + e1.x;   // vec0: t1..t4
            o4.y = e1.z + e1.w + e2.x + e2.y;   // vec1
            o4.z = e2.w + e3.x + e3.y + e3.z;   // vec2
            o4.w = e4.x + e4.y + e4.z + e4.w;   // vec3
            *(float4*)(Asum + ch * 1024 + tid * 4) = o4;
            // store next chunk into the other buffer
            if (ch < 15) {
                float4* d4 = (float4*)(stage + ((ch + 1) & 1) * 5120);
                #pragma unroll
                for (int k = 0; k < 5; k++) d4[tid + NTHREADS * k] = rr[k];
            }
            __syncthreads();
        }

        // ---- deg[i] = row sum; w0 = 1/(V*deg) ----
        for (int i = wid; i < VN; i += 8) {
            float acc = 0.f;
            #pragma unroll
            for (int u = 0; u < 4; u++) acc += Asum[i * VN + lane + 32 * u];
            #pragma unroll
            for (int o = 16; o; o >>= 1)
                acc += __shfl_xor_sync(0xffffffffu, acc, o);
            if (lane == 0) {
                float d = fmaxf(acc, 1e-8f);
                deg[i] = d;
                w0[i]  = 1.f / (d * (float)VN);
            }
        }
        __syncthreads();

        // ---- r1 = Asum^T w0 ; r2 ; r3 ----
        if (tid < VN) {
            float acc = 0.f;
            #pragma unroll 8
            for (int i = 0; i < VN; i++) acc += Asum[i * VN + tid] * w0[i];
            rA[tid] = acc;                       // r1
        }
        __syncthreads();
        if (tid < VN) w0[tid] = rA[tid] / deg[tid];
        __syncthreads();
        if (tid < VN) {
            float acc = 0.f;
            #pragma unroll 8
            for (int i = 0; i < VN; i++) acc += Asum[i * VN + tid] * w0[i];
            rA[tid] = acc;                       // r2
        }
        __syncthreads();
        if (tid < VN) w0[tid] = rA[tid] / deg[tid];
        __syncthreads();
        if (tid < VN) {
            float acc = 0.f;
            #pragma unroll 8
            for (int i = 0; i < VN; i++) acc += Asum[i * VN + tid] * w0[i];
            rB[tid] = acc;                       // r3
        }
        __syncthreads();

        // ---- 28 weight-independent sums -> g_sums ----
        for (int o = wid; o < 28; o += 8) {
            const float* r = (o >= 14) ? rB : rA;
            int m = (o >= 14) ? o - 14 : o;
            float acc = 0.f;
            #pragma unroll 4
            for (int j = lane; j < VN; j += 32) {
                float x;
                if (m < 5)       x = nodes[((size_t)b * VN + j) * 5 + m];
                else if (m < 13) x = nparams[((size_t)b * VN + j) * 8 + (m - 5)];
                else             x = 1.f;
                acc += r[j] * x;
            }
            #pragma unroll
            for (int off = 16; off; off >>= 1)
                acc += __shfl_xor_sync(0xffffffffu, acc, off);
            if (lane == 0) g_sums[b * 28 + o] = acc;
        }
    }

    // ---- last-block combine ----
    __threadfence();
    __syncthreads();
    __shared__ int s_old;
    if (tid == 0) s_old = atomicAdd(&g_count, 1);
    __syncthreads();
    if (s_old == 512) {
        float c[43];
        #pragma unroll
        for (int i = 0; i < 43; i++) c[i] = __ldcg(&g_cst[i]);
        for (int b2 = tid; b2 < 512; b2 += NTHREADS) {
            const float* S = &g_sums[b2 * 28];
            float acc = c[38] + c[36] * __ldcg(&S[13]) + c[37] * __ldcg(&S[27]);
            #pragma unroll
            for (int m = 0; m < 5; m++)
                acc += c[m] * __ldcg(&S[m]) + c[5 + m] * __ldcg(&S[14 + m]);
            #pragma unroll
            for (int m = 0; m < 8; m++)
                acc += c[10 + m] * __ldcg(&S[5 + m]) + c[18 + m] * __ldcg(&S[19 + m]);
            const float* cd = cond + (size_t)b2 * 10;
            #pragma unroll
            for (int m = 0; m < 10; m++) acc += c[26 + m] * cd[m];
            out[b2] = acc;
        }
        if (tid == 0) g_count = 0;   // reset for next graph replay
    }
}

extern "C" void kernel_launch(void* const* d_in, const int* in_sizes, int n_in,
                              void* d_out, int out_size) {
    cudaFuncSetAttribute(gnn_fused, cudaFuncAttributeMaxDynamicSharedMemorySize,
                         SMEM_BYTES);

    gnn_fused<<<513, NTHREADS, SMEM_BYTES>>>(
        (const float*)d_in[0], (const float*)d_in[1],
        (const float*)d_in[2], (const float*)d_in[3],
        (float*)d_out,
        (const float*)d_in[4],  (const float*)d_in[5],
        (const float*)d_in[6],  (const float*)d_in[7],
        (const float*)d_in[8],  (const float*)d_in[9],
        (const float*)d_in[10], (const float*)d_in[11],
        (const float*)d_in[12], (const float*)d_in[13],
        (const float*)d_in[14], (const float*)d_in[15],
        (const float*)d_in[16], (const float*)d_in[17],
        (const float*)d_in[18], (const float*)d_in[19],
        (const float*)d_in[20], (const float*)d_in[21],
        (const float*)d_in[22], (const float*)d_in[23],
        (const float*)d_in[24], (const float*)d_in[25],
        (const float*)d_in[26], (const float*)d_in[27]);
}